// round 5
// baseline (speedup 1.0000x reference)
#include <cuda_runtime.h>

// DeltaSynapse: I[b,o] = sum_e Weff[b,e,o] * sum_d (Xd[d,b,e]*(Wshort[d,b,e]+1)) * delaymap[d,e,o]
// Weff[b,e,o] = sg[e,o]*(W[e,o]*(1-frac[e,o]) + Wlong[b,e,o]*frac[e,o])
// sg[e,o] = (W[e,o] > 0) ? sign(signs_pre[e]) : 0
//
// D=8, B=16, N=2048. HBM-bound (~417 MB unique -> ~66us floor).
// R3: float4 streams (4 o per thread) -> 4x bytes-in-flight per warp.
// 256 thr, 2 CTA/SM, grid 2x128 = 256 CTAs (one wave in 296 slots).

#define NN 2048
#define BB 16
#define DD 8
#define ECHUNK 16
#define THREADS 256
#define OTILE (THREADS * 4)

__global__ void ds_zero_kernel(float* __restrict__ out, int n) {
    int i = blockIdx.x * blockDim.x + threadIdx.x;
    if (i < n) out[i] = 0.0f;
}

__global__ __launch_bounds__(THREADS, 2) void ds_main_kernel(
    const float* __restrict__ W,         // (N,N)
    const float* __restrict__ Wlong,     // (B,N,N)
    const float* __restrict__ Wshort,    // (D,B,N)
    const float* __restrict__ Xd,        // (D,B,N)
    const float* __restrict__ delaymap,  // (D,N,N)
    const float* __restrict__ frac,      // (N,N)
    const float* __restrict__ signs_pre, // (N,)
    float* __restrict__ out)             // (B,N)
{
    __shared__ float coef[ECHUNK][DD * BB]; // [e_local][d*BB + b]
    __shared__ float sgn_sh[ECHUNK];

    const int tid = threadIdx.x;
    const int o   = blockIdx.x * OTILE + tid * 4;
    const int e0  = blockIdx.y * ECHUNK;

    // Cooperative preload of coef for this e-chunk (coalesced in e).
    for (int idx = tid; idx < DD * BB * ECHUNK; idx += THREADS) {
        int el = idx % ECHUNK;
        int b  = (idx / ECHUNK) % BB;
        int d  = idx / (ECHUNK * BB);
        int gi = (d * BB + b) * NN + (e0 + el);
        coef[el][d * BB + b] = Xd[gi] * (Wshort[gi] + 1.0f);
    }
    if (tid < ECHUNK) {
        float sp = signs_pre[e0 + tid];
        sgn_sh[tid] = (sp > 0.0f) ? 1.0f : ((sp < 0.0f) ? -1.0f : 0.0f);
    }
    __syncthreads();

    float4 acc[BB];
#pragma unroll
    for (int b = 0; b < BB; b++) acc[b] = make_float4(0.f, 0.f, 0.f, 0.f);

    for (int el = 0; el < ECHUNK; el++) {
        const int e = e0 + el;
        const long base_eo = (long)e * NN + o;

        const float4 w4 = *(const float4*)(W + base_eo);
        const float4 f4 = *(const float4*)(frac + base_eo);
        const float se = sgn_sh[el];

        float4 sg;
        sg.x = (w4.x > 0.0f) ? se : 0.0f;
        sg.y = (w4.y > 0.0f) ? se : 0.0f;
        sg.z = (w4.z > 0.0f) ? se : 0.0f;
        sg.w = (w4.w > 0.0f) ? se : 0.0f;

        float4 cbase, fs;
        cbase.x = sg.x * w4.x * (1.0f - f4.x);  fs.x = sg.x * f4.x;
        cbase.y = sg.y * w4.y * (1.0f - f4.y);  fs.y = sg.y * f4.y;
        cbase.z = sg.z * w4.z * (1.0f - f4.z);  fs.z = sg.z * f4.z;
        cbase.w = sg.w * w4.w * (1.0f - f4.w);  fs.w = sg.w * f4.w;

        float4 dm[DD];
#pragma unroll
        for (int d = 0; d < DD; d++)
            dm[d] = *(const float4*)(delaymap + (long)d * NN * NN + base_eo);

        // Wlong streamed in pairs; fully unrolled so ptxas can hoist loads.
#pragma unroll
        for (int h = 0; h < BB / 2; h++) {
            float4 wl0 = *(const float4*)(Wlong + (long)(2 * h + 0) * NN * NN + base_eo);
            float4 wl1 = *(const float4*)(Wlong + (long)(2 * h + 1) * NN * NN + base_eo);

#pragma unroll
            for (int j = 0; j < 2; j++) {
                const int b = 2 * h + j;
                const float4 wl = (j == 0) ? wl0 : wl1;

                float4 p = make_float4(0.f, 0.f, 0.f, 0.f);
#pragma unroll
                for (int d = 0; d < DD; d++) {
                    const float c = coef[el][d * BB + b];
                    p.x = fmaf(dm[d].x, c, p.x);
                    p.y = fmaf(dm[d].y, c, p.y);
                    p.z = fmaf(dm[d].z, c, p.z);
                    p.w = fmaf(dm[d].w, c, p.w);
                }
                float4 weff;
                weff.x = fmaf(fs.x, wl.x, cbase.x);
                weff.y = fmaf(fs.y, wl.y, cbase.y);
                weff.z = fmaf(fs.z, wl.z, cbase.z);
                weff.w = fmaf(fs.w, wl.w, cbase.w);

                acc[b].x = fmaf(weff.x, p.x, acc[b].x);
                acc[b].y = fmaf(weff.y, p.y, acc[b].y);
                acc[b].z = fmaf(weff.z, p.z, acc[b].z);
                acc[b].w = fmaf(weff.w, p.w, acc[b].w);
            }
        }
    }

#pragma unroll
    for (int b = 0; b < BB; b++) {
        atomicAdd(&out[b * NN + o + 0], acc[b].x);
        atomicAdd(&out[b * NN + o + 1], acc[b].y);
        atomicAdd(&out[b * NN + o + 2], acc[b].z);
        atomicAdd(&out[b * NN + o + 3], acc[b].w);
    }
}

extern "C" void kernel_launch(void* const* d_in, const int* in_sizes, int n_in,
                              void* d_out, int out_size) {
    const float* W         = (const float*)d_in[0];
    const float* Wlong     = (const float*)d_in[1];
    const float* Wshort    = (const float*)d_in[2];
    const float* Xd        = (const float*)d_in[3];
    const float* delaymap  = (const float*)d_in[4];
    const float* STDP_frac = (const float*)d_in[5];
    const float* signs_pre = (const float*)d_in[6];
    float* out = (float*)d_out;

    ds_zero_kernel<<<(BB * NN + 255) / 256, 256>>>(out, BB * NN);

    dim3 grid(NN / OTILE, NN / ECHUNK); // (2, 128) = 256 CTAs
    ds_main_kernel<<<grid, THREADS>>>(W, Wlong, Wshort, Xd, delaymap,
                                      STDP_frac, signs_pre, out);
}

// round 6
// speedup vs baseline: 1.1350x; 1.1350x over previous
#include <cuda_runtime.h>

// DeltaSynapse: I[b,o] = sum_e Weff[b,e,o] * sum_d (Xd[d,b,e]*(Wshort[d,b,e]+1)) * delaymap[d,e,o]
// Weff[b,e,o] = sg[e,o]*(W[e,o]*(1-frac[e,o]) + Wlong[b,e,o]*frac[e,o])
// sg[e,o] = (W[e,o] > 0) ? sign(signs_pre[e]) : 0
//
// D=8, B=16, N=2048. HBM-bound (~417 MB -> ~66us floor).
// R5: crossbar fix — coef reads via LDS.128 broadcast (32 ops/e-iter instead
// of 128 scalar LDS). Globals stay scalar 32-bit (R4 showed float4 streams
// destroy MLP via register pressure). 128-thr CTAs, 5 CTA/SM, 512-CTA grid
// = single balanced wave.

#define NN 2048
#define BB 16
#define DD 8
#define ECHUNK 64
#define THREADS 128
#define OTILE 128

__global__ void ds_zero_kernel(float* __restrict__ out, int n) {
    int i = blockIdx.x * blockDim.x + threadIdx.x;
    if (i < n) out[i] = 0.0f;
}

__global__ __launch_bounds__(THREADS, 5) void ds_main_kernel(
    const float* __restrict__ W,         // (N,N)
    const float* __restrict__ Wlong,     // (B,N,N)
    const float* __restrict__ Wshort,    // (D,B,N)
    const float* __restrict__ Xd,        // (D,B,N)
    const float* __restrict__ delaymap,  // (D,N,N)
    const float* __restrict__ frac,      // (N,N)
    const float* __restrict__ signs_pre, // (N,)
    float* __restrict__ out)             // (B,N)
{
    // coef4[el][d][g] holds coef for b = 4g..4g+3 (b contiguous -> LDS.128)
    __shared__ float4 coef4[ECHUNK][DD][BB / 4]; // 32 KB
    __shared__ float sgn_sh[ECHUNK];

    const int tid = threadIdx.x;
    const int o   = blockIdx.x * OTILE + tid;
    const int e0  = blockIdx.y * ECHUNK;

    // Cooperative preload of coef (global loads coalesced in e).
    {
        float* cf = (float*)coef4;
        for (int idx = tid; idx < DD * BB * ECHUNK; idx += THREADS) {
            int el   = idx % ECHUNK;
            int rest = idx / ECHUNK;
            int b    = rest % BB;
            int d    = rest / BB;
            int gi   = (d * BB + b) * NN + (e0 + el);
            cf[(el * DD + d) * BB + b] = Xd[gi] * (Wshort[gi] + 1.0f);
        }
    }
    if (tid < ECHUNK) {
        float sp = signs_pre[e0 + tid];
        sgn_sh[tid] = (sp > 0.0f) ? 1.0f : ((sp < 0.0f) ? -1.0f : 0.0f);
    }
    __syncthreads();

    float acc[BB];
#pragma unroll
    for (int b = 0; b < BB; b++) acc[b] = 0.0f;

    for (int el = 0; el < ECHUNK; el++) {
        const int e = e0 + el;
        const long base_eo = (long)e * NN + o;

        const float w  = W[base_eo];
        const float f  = frac[base_eo];
        const float se = sgn_sh[el];
        const float sg = (w > 0.0f) ? se : 0.0f;
        const float cbase = sg * w * (1.0f - f);
        const float fs    = sg * f;

        float dm[DD];
#pragma unroll
        for (int d = 0; d < DD; d++)
            dm[d] = delaymap[(long)d * NN * NN + base_eo];

        float wl[BB];
#pragma unroll
        for (int b = 0; b < BB; b++)
            wl[b] = Wlong[(long)b * NN * NN + base_eo];

#pragma unroll
        for (int g = 0; g < BB / 4; g++) {
            float4 p = make_float4(0.f, 0.f, 0.f, 0.f);
#pragma unroll
            for (int d = 0; d < DD; d++) {
                const float4 c = coef4[el][d][g];   // LDS.128 broadcast
                p.x = fmaf(dm[d], c.x, p.x);
                p.y = fmaf(dm[d], c.y, p.y);
                p.z = fmaf(dm[d], c.z, p.z);
                p.w = fmaf(dm[d], c.w, p.w);
            }
            const int b0 = 4 * g;
            acc[b0 + 0] = fmaf(fmaf(fs, wl[b0 + 0], cbase), p.x, acc[b0 + 0]);
            acc[b0 + 1] = fmaf(fmaf(fs, wl[b0 + 1], cbase), p.y, acc[b0 + 1]);
            acc[b0 + 2] = fmaf(fmaf(fs, wl[b0 + 2], cbase), p.z, acc[b0 + 2]);
            acc[b0 + 3] = fmaf(fmaf(fs, wl[b0 + 3], cbase), p.w, acc[b0 + 3]);
        }
    }

#pragma unroll
    for (int b = 0; b < BB; b++)
        atomicAdd(&out[b * NN + o], acc[b]);
}

extern "C" void kernel_launch(void* const* d_in, const int* in_sizes, int n_in,
                              void* d_out, int out_size) {
    const float* W         = (const float*)d_in[0];
    const float* Wlong     = (const float*)d_in[1];
    const float* Wshort    = (const float*)d_in[2];
    const float* Xd        = (const float*)d_in[3];
    const float* delaymap  = (const float*)d_in[4];
    const float* STDP_frac = (const float*)d_in[5];
    const float* signs_pre = (const float*)d_in[6];
    float* out = (float*)d_out;

    ds_zero_kernel<<<(BB * NN + 255) / 256, 256>>>(out, BB * NN);

    dim3 grid(NN / OTILE, NN / ECHUNK); // (16, 32) = 512 CTAs
    ds_main_kernel<<<grid, THREADS>>>(W, Wlong, Wshort, Xd, delaymap,
                                      STDP_frac, signs_pre, out);
}